// round 9
// baseline (speedup 1.0000x reference)
#include <cuda_runtime.h>
#include <cuda_bf16.h>
#include <cstdint>

#define NN   50000
#define NE   1600000
#define D    128
#define NCLS 6
#define NBLK 49          // ceil(NN / 1024) scan blocks

// ---------------- scratch (static device globals; no runtime allocation) ----
__device__ float g_agg12[NN * 12];
__device__ float g_h[(size_t)NN * D];
__device__ float g_agg[(size_t)NN * D];
__device__ int   g_counts[NN];
__device__ int   g_rowptr[NN + 1];
__device__ int   g_cursor[NN];
__device__ int   g_col[NE];
__device__ int   g_blocksums[64];
__device__ int   g_blockoffs[64];
__device__ int   g_is64;   // 1 if edge_index really is int64, 0 if int32

// ---------------- small helpers ---------------------------------------------
__device__ __forceinline__ uint32_t smem_to_u32(const void* p) {
    uint32_t a;
    asm("{ .reg .u64 t; cvta.to.shared.u64 t, %1; cvt.u32.u64 %0, t; }"
        : "=r"(a) : "l"(p));
    return a;
}
__device__ __forceinline__ uint32_t lds32(uint32_t addr) {
    uint32_t v;
    asm volatile("ld.shared.b32 %0, [%1];" : "=r"(v) : "r"(addr));
    return v;
}
__device__ __forceinline__ void sts32(uint32_t addr, uint32_t v) {
    asm volatile("st.shared.b32 [%0], %1;" :: "r"(addr), "r"(v) : "memory");
}
// split two fp32 into bf16 hi/lo packed pairs
__device__ __forceinline__ void split2(float x, float y, uint32_t& hi, uint32_t& lo) {
    __nv_bfloat16 xh = __float2bfloat16(x), yh = __float2bfloat16(y);
    float xr = x - __bfloat162float(xh);
    float yr = y - __bfloat162float(yh);
    __nv_bfloat16 xl = __float2bfloat16(xr), yl = __float2bfloat16(yr);
    hi = ((uint32_t)__bfloat16_as_ushort(yh) << 16) | __bfloat16_as_ushort(xh);
    lo = ((uint32_t)__bfloat16_as_ushort(yl) << 16) | __bfloat16_as_ushort(xl);
}
__device__ __forceinline__ void mma16816(float* c, const uint32_t* a, const uint32_t* b) {
    asm volatile(
        "mma.sync.aligned.m16n8k16.row.col.f32.bf16.bf16.f32 "
        "{%0,%1,%2,%3},{%4,%5,%6,%7},{%8,%9},{%0,%1,%2,%3};"
        : "+f"(c[0]), "+f"(c[1]), "+f"(c[2]), "+f"(c[3])
        : "r"(a[0]), "r"(a[1]), "r"(a[2]), "r"(a[3]), "r"(b[0]), "r"(b[1]));
}

// ---------------- smem tile layouts ------------------------------------------
#define KS 136                       // bf16 elems per row (padded)
// A tile: [row][k]
__device__ __forceinline__ uint32_t a_off(int r, int k) {
    return (uint32_t)(r * KS + k) * 2;
}
// W tile: [n][k] with XOR swizzle on k bits 1..2 keyed by (n>>3)&3 —
// conflict-free for both transpose stores and b-fragment loads.
__device__ __forceinline__ uint32_t wt_off(int n, int k) {
    return (uint32_t)(n * KS + (k ^ ((((unsigned)n >> 3) & 3) << 1))) * 2;
}

#define SM_AHI   0
#define SM_ALO   34816
#define SM_W1HI  69632
#define SM_W1LO  104448
#define SM_W2HI  139264
#define SM_W2LO  174080
#define SM_PAR   208896              // 640 floats: b1|b2|sc|mn|bt
#define SM_TOTAL 211456

// ---------------- edge-index dtype detection --------------------------------
__global__ void detect_kernel(const void* ei) {
    const long long* p = (const long long*)ei;
    int ok = 1;
    for (int i = 0; i < 64; i++) {
        long long v = p[i];
        if (v < 0 || v >= NN) { ok = 0; break; }
    }
    g_is64 = ok;
}
__device__ __forceinline__ int edge_idx(const void* ei, long long pos, int is64) {
    if (is64) return (int)((const long long*)ei)[pos];
    return ((const int*)ei)[pos];
}

// ---------------- CSR build --------------------------------------------------
__global__ void zero_counts_kernel() {
    int i = blockIdx.x * blockDim.x + threadIdx.x;
    if (i < NN) g_counts[i] = 0;
}
__global__ void hist_kernel(const void* __restrict__ ei) {
    int e = blockIdx.x * blockDim.x + threadIdx.x;
    if (e >= NE) return;
    const int is64 = g_is64;
    int dst = edge_idx(ei, (long long)NE + e, is64);
    if ((unsigned)dst < NN) atomicAdd(&g_counts[dst], 1);
}
__global__ void scan_reduce_kernel() {
    __shared__ int sh[256];
    int base = blockIdx.x * 1024;
    int s = 0;
    for (int i = threadIdx.x; i < 1024; i += 256) {
        int idx = base + i;
        if (idx < NN) s += g_counts[idx];
    }
    sh[threadIdx.x] = s;
    __syncthreads();
    for (int off = 128; off > 0; off >>= 1) {
        if (threadIdx.x < off) sh[threadIdx.x] += sh[threadIdx.x + off];
        __syncthreads();
    }
    if (threadIdx.x == 0) g_blocksums[blockIdx.x] = sh[0];
}
__global__ void scan_sums_kernel() {
    __shared__ int sh[NBLK];
    if (threadIdx.x < NBLK) sh[threadIdx.x] = g_blocksums[threadIdx.x];
    __syncthreads();
    if (threadIdx.x == 0) {
        int run = 0;
        for (int i = 0; i < NBLK; i++) { int v = sh[i]; sh[i] = run; run += v; }
        g_rowptr[NN] = run;
    }
    __syncthreads();
    if (threadIdx.x < NBLK) g_blockoffs[threadIdx.x] = sh[threadIdx.x];
}
__global__ void scan_final_kernel() {
    __shared__ int sh[1024];
    int i = blockIdx.x * 1024 + threadIdx.x;
    int v = (i < NN) ? g_counts[i] : 0;
    sh[threadIdx.x] = v;
    __syncthreads();
#pragma unroll
    for (int off = 1; off < 1024; off <<= 1) {
        int t = (threadIdx.x >= off) ? sh[threadIdx.x - off] : 0;
        __syncthreads();
        sh[threadIdx.x] += t;
        __syncthreads();
    }
    if (i < NN) {
        int excl = g_blockoffs[blockIdx.x] + sh[threadIdx.x] - v;
        g_rowptr[i] = excl;
        g_cursor[i] = excl;
    }
}
__global__ void fill_kernel(const void* __restrict__ ei) {
    int e = blockIdx.x * blockDim.x + threadIdx.x;
    if (e >= NE) return;
    const int is64 = g_is64;
    int src = edge_idx(ei, e, is64);
    int dst = edge_idx(ei, (long long)NE + e, is64);
    if ((unsigned)src >= NN || (unsigned)dst >= NN) return;
    int pos = atomicAdd(&g_cursor[dst], 1);
    g_col[pos] = src;
}

// ---------------- CSR gather: agg[n] = x[n] + sum_{j in N(n)} x[j] ----------
__global__ void gather12_kernel(const float* __restrict__ x) {
    int n = (blockIdx.x * blockDim.x + threadIdx.x) >> 5;
    if (n >= NN) return;
    int lane = threadIdx.x & 31;
    int beg = g_rowptr[n], end = g_rowptr[n + 1];
    float acc = (lane < 12) ? x[(size_t)n * 12 + lane] : 0.f;
    for (int e = beg; e < end; e++) {
        int s = g_col[e];
        if (lane < 12) acc += x[(size_t)s * 12 + lane];
    }
    if (lane < 12) g_agg12[(size_t)n * 12 + lane] = acc;
}
__global__ void gather128_kernel(const float* __restrict__ h,
                                 float* __restrict__ agg) {
    int n = (blockIdx.x * blockDim.x + threadIdx.x) >> 5;
    if (n >= NN) return;
    int lane = threadIdx.x & 31;
    int beg = g_rowptr[n], end = g_rowptr[n + 1];
    float4 acc = reinterpret_cast<const float4*>(h + (size_t)n * D)[lane];
    float4 acc2 = make_float4(0.f, 0.f, 0.f, 0.f);
    int e = beg;
    for (; e + 1 < end; e += 2) {
        int s0 = g_col[e];
        int s1 = g_col[e + 1];
        float4 v0 = reinterpret_cast<const float4*>(h + (size_t)s0 * D)[lane];
        float4 v1 = reinterpret_cast<const float4*>(h + (size_t)s1 * D)[lane];
        acc.x += v0.x;  acc.y += v0.y;  acc.z += v0.z;  acc.w += v0.w;
        acc2.x += v1.x; acc2.y += v1.y; acc2.z += v1.z; acc2.w += v1.w;
    }
    if (e < end) {
        int s = g_col[e];
        float4 v = reinterpret_cast<const float4*>(h + (size_t)s * D)[lane];
        acc.x += v.x; acc.y += v.y; acc.z += v.z; acc.w += v.w;
    }
    acc.x += acc2.x; acc.y += acc2.y; acc.z += acc2.z; acc.w += acc2.w;
    reinterpret_cast<float4*>(agg + (size_t)n * D)[lane] = acc;
}

// ============================================================================
// mma.sync fused MLP: 128-row tile per CTA, 256 threads (8 warps).
// Warp (wr, wc): rows [32wr,32wr+32) as 2 m16 tiles, cols [64wc,64wc+64) as
// 8 n8 tiles. B fragments amortized over 2 m-tiles: 48 LDS per 48 MMAs.
// bf16 hi/lo split, 3 passes (Ahi*Whi + Alo*Whi + Ahi*Wlo), fp32 accum.
// head==0: out = BN(relu( relu(A@W1+b1) @ W2 + b2 ));  head==1: fc1+fc2.
// ============================================================================
__device__ __forceinline__ void gemm_split(
    uint32_t aHi, uint32_t aLo, uint32_t wHi, uint32_t wLo,
    int r0, int cc, int n0, int lane, float acc[2][8][4], int kpad) {
#pragma unroll 1
    for (int kb = 0; kb < kpad; kb += 16) {
        uint32_t ah[2][4], al[2][4];
#pragma unroll
        for (int m = 0; m < 2; m++) {
            int rm = r0 + m * 16;
            ah[m][0] = lds32(aHi + a_off(rm,     kb + cc));
            ah[m][1] = lds32(aHi + a_off(rm + 8, kb + cc));
            ah[m][2] = lds32(aHi + a_off(rm,     kb + cc + 8));
            ah[m][3] = lds32(aHi + a_off(rm + 8, kb + cc + 8));
            al[m][0] = lds32(aLo + a_off(rm,     kb + cc));
            al[m][1] = lds32(aLo + a_off(rm + 8, kb + cc));
            al[m][2] = lds32(aLo + a_off(rm,     kb + cc + 8));
            al[m][3] = lds32(aLo + a_off(rm + 8, kb + cc + 8));
        }
#pragma unroll
        for (int t = 0; t < 8; t++) {
            int nl = n0 + t * 8 + (lane >> 2);
            uint32_t bh[2], bl[2];
            bh[0] = lds32(wHi + wt_off(nl, kb + cc));
            bh[1] = lds32(wHi + wt_off(nl, kb + cc + 8));
            bl[0] = lds32(wLo + wt_off(nl, kb + cc));
            bl[1] = lds32(wLo + wt_off(nl, kb + cc + 8));
            mma16816(acc[0][t], ah[0], bh);
            mma16816(acc[1][t], ah[1], bh);
            mma16816(acc[0][t], al[0], bh);
            mma16816(acc[1][t], al[1], bh);
            mma16816(acc[0][t], ah[0], bl);
            mma16816(acc[1][t], ah[1], bl);
        }
    }
}

template <int KIN, int KPAD>
__global__ __launch_bounds__(256, 1) void mlp_mma(
    const float* __restrict__ A,
    const float* __restrict__ W1, const float* __restrict__ b1,
    const float* __restrict__ W2, const float* __restrict__ b2,
    const float* __restrict__ gamma, const float* __restrict__ beta,
    const float* __restrict__ mean, const float* __restrict__ var,
    float* __restrict__ out, int head) {
    extern __shared__ char smem[];
    const uint32_t sb = smem_to_u32(smem);
    const int tid = threadIdx.x;
    const int lane = tid & 31;
    const int wid = tid >> 5;
    const int wr = wid >> 1, wc = wid & 1;    // 4 x 2 warps
    const int row0 = blockIdx.x * 128;

    const uint32_t AHI = sb + SM_AHI, ALO = sb + SM_ALO;
    const uint32_t W1HI = sb + SM_W1HI, W1LO = sb + SM_W1LO;
    const uint32_t W2HI = sb + SM_W2HI, W2LO = sb + SM_W2LO;
    float* par = (float*)(smem + SM_PAR);   // b1[128] b2[128] sc[128] mn[128] bt[128]

    // ---- stage A [row][k] hi/lo: thread = (row, half of k) ----
    {
        int r = tid >> 1;
        int q = (tid & 1) * (KPAD / 2);
        int gr = row0 + r;
        const float* ar = A + (size_t)gr * KIN;
        bool ok = gr < NN;
#pragma unroll
        for (int j = 0; j < KPAD / 8; j++) {
            int k = q + j * 4;
            float4 v = make_float4(0.f, 0.f, 0.f, 0.f);
            if (ok) {
                if (k + 3 < KIN) v = *reinterpret_cast<const float4*>(ar + k);
                else {
                    if (k     < KIN) v.x = ar[k];
                    if (k + 1 < KIN) v.y = ar[k + 1];
                    if (k + 2 < KIN) v.z = ar[k + 2];
                    if (k + 3 < KIN) v.w = ar[k + 3];
                }
            }
            uint32_t h0, l0, h1, l1;
            split2(v.x, v.y, h0, l0);
            split2(v.z, v.w, h1, l1);
            sts32(AHI + a_off(r, k),     h0);
            sts32(AHI + a_off(r, k + 2), h1);
            sts32(ALO + a_off(r, k),     l0);
            sts32(ALO + a_off(r, k + 2), l1);
        }
    }
    // ---- stage W1 transposed [n][k] hi/lo (coalesced gmem reads) ----
    {
        int n = tid & 127;
        int kh = (tid >> 7) * (KPAD / 2);   // 0 or KPAD/2
        for (int kk = 0; kk < KPAD / 2; kk += 2) {
            int k = kh + kk;
            float v0 = (k     < KIN) ? __ldg(W1 + (size_t)k * D + n) : 0.f;
            float v1 = (k + 1 < KIN) ? __ldg(W1 + (size_t)(k + 1) * D + n) : 0.f;
            uint32_t hi, lo;
            split2(v0, v1, hi, lo);
            sts32(W1HI + wt_off(n, k), hi);
            sts32(W1LO + wt_off(n, k), lo);
        }
    }
    // ---- stage W2 ----
    if (!head) {
        int n = tid & 127;
        int kh = (tid >> 7) * 64;
        for (int kk = 0; kk < 64; kk += 2) {
            int k = kh + kk;
            float v0 = __ldg(W2 + (size_t)k * D + n);
            float v1 = __ldg(W2 + (size_t)(k + 1) * D + n);
            uint32_t hi, lo;
            split2(v0, v1, hi, lo);
            sts32(W2HI + wt_off(n, k), hi);
            sts32(W2LO + wt_off(n, k), lo);
        }
    } else {
        float* w2f = (float*)(smem + SM_W2HI);
        for (int i = tid; i < D * NCLS; i += 256) w2f[i] = __ldg(W2 + i);
    }
    // ---- stage params ----
    if (tid < 128) {
        par[tid] = __ldg(b1 + tid);
        if (!head) {
            par[128 + tid] = __ldg(b2 + tid);
            par[256 + tid] = __ldg(gamma + tid) * rsqrtf(__ldg(var + tid) + 1e-5f);
            par[384 + tid] = __ldg(mean + tid);
            par[512 + tid] = __ldg(beta + tid);
        } else if (tid < NCLS) {
            par[128 + tid] = __ldg(b2 + tid);
        }
    }
    __syncthreads();

    const int r0 = wr * 32 + (lane >> 2);
    const int cc = (lane & 3) * 2;
    const int n0 = wc * 64;

    // ---- GEMM1 ----
    float acc[2][8][4];
#pragma unroll
    for (int m = 0; m < 2; m++)
#pragma unroll
        for (int t = 0; t < 8; t++)
#pragma unroll
            for (int j = 0; j < 4; j++) acc[m][t][j] = 0.f;
    gemm_split(AHI, ALO, W1HI, W1LO, r0, cc, n0, lane, acc, KPAD);
    __syncthreads();   // all A/W1 reads done before overwriting A with T

    // ---- epilogue1: T = relu(acc + b1) -> back into A slots ----
    if (!head) {
#pragma unroll
        for (int m = 0; m < 2; m++) {
            int rm = r0 + m * 16;
#pragma unroll
            for (int t = 0; t < 8; t++) {
                int c0 = n0 + t * 8 + cc;
                float x0 = fmaxf(acc[m][t][0] + par[c0], 0.f);
                float x1 = fmaxf(acc[m][t][1] + par[c0 + 1], 0.f);
                float x2 = fmaxf(acc[m][t][2] + par[c0], 0.f);
                float x3 = fmaxf(acc[m][t][3] + par[c0 + 1], 0.f);
                uint32_t h, l;
                split2(x0, x1, h, l);
                sts32(AHI + a_off(rm, c0), h);
                sts32(ALO + a_off(rm, c0), l);
                split2(x2, x3, h, l);
                sts32(AHI + a_off(rm + 8, c0), h);
                sts32(ALO + a_off(rm + 8, c0), l);
            }
        }
    } else {
        float* Tf = (float*)(smem + SM_AHI);   // fp32, stride 132
#pragma unroll
        for (int m = 0; m < 2; m++) {
            int rm = r0 + m * 16;
#pragma unroll
            for (int t = 0; t < 8; t++) {
                int c0 = n0 + t * 8 + cc;
                Tf[rm * 132 + c0]           = fmaxf(acc[m][t][0] + par[c0], 0.f);
                Tf[rm * 132 + c0 + 1]       = fmaxf(acc[m][t][1] + par[c0 + 1], 0.f);
                Tf[(rm + 8) * 132 + c0]     = fmaxf(acc[m][t][2] + par[c0], 0.f);
                Tf[(rm + 8) * 132 + c0 + 1] = fmaxf(acc[m][t][3] + par[c0 + 1], 0.f);
            }
        }
    }
    __syncthreads();

    if (head) {
        // ---- fc2 SIMT: out[128x6] = T @ W2 + b2 ----
        if (tid < 128) {
            const float* Tf = (const float*)(smem + SM_AHI);
            const float* Wf = (const float*)(smem + SM_W2HI);
            float a6[NCLS];
#pragma unroll
            for (int c = 0; c < NCLS; c++) a6[c] = par[128 + c];
            for (int kk = 0; kk < D; kk++) {
                int k = (kk + lane) & (D - 1);
                float tv = Tf[tid * 132 + k];
#pragma unroll
                for (int c = 0; c < NCLS; c++) a6[c] += tv * Wf[k * NCLS + c];
            }
            if (row0 + tid < NN)
#pragma unroll
                for (int c = 0; c < NCLS; c++) out[(size_t)(row0 + tid) * NCLS + c] = a6[c];
        }
        return;
    }

    // ---- GEMM2 ----
#pragma unroll
    for (int m = 0; m < 2; m++)
#pragma unroll
        for (int t = 0; t < 8; t++)
#pragma unroll
            for (int j = 0; j < 4; j++) acc[m][t][j] = 0.f;
    gemm_split(AHI, ALO, W2HI, W2LO, r0, cc, n0, lane, acc, 128);

    // ---- epilogue2: BN(relu(acc + b2)) -> gmem ----
#pragma unroll
    for (int m = 0; m < 2; m++) {
        int g0 = row0 + r0 + m * 16, g1 = g0 + 8;
#pragma unroll
        for (int t = 0; t < 8; t++) {
            int c0 = n0 + t * 8 + cc;
            float b0v = par[128 + c0], b1v = par[128 + c0 + 1];
            float s0 = par[256 + c0],  s1 = par[256 + c0 + 1];
            float m0 = par[384 + c0],  m1 = par[384 + c0 + 1];
            float t0 = par[512 + c0],  t1 = par[512 + c0 + 1];
            if (g0 < NN) {
                float v0 = (fmaxf(acc[m][t][0] + b0v, 0.f) - m0) * s0 + t0;
                float v1 = (fmaxf(acc[m][t][1] + b1v, 0.f) - m1) * s1 + t1;
                *reinterpret_cast<float2*>(out + (size_t)g0 * D + c0) = make_float2(v0, v1);
            }
            if (g1 < NN) {
                float v2 = (fmaxf(acc[m][t][2] + b0v, 0.f) - m0) * s0 + t0;
                float v3 = (fmaxf(acc[m][t][3] + b1v, 0.f) - m1) * s1 + t1;
                *reinterpret_cast<float2*>(out + (size_t)g1 * D + c0) = make_float2(v2, v3);
            }
        }
    }
}

// ---------------- launch ----------------------------------------------------
extern "C" void kernel_launch(void* const* d_in, const int* in_sizes, int n_in,
                              void* d_out, int out_size) {
    const float* x      = (const float*)d_in[0];
    const void*  ei     = (const void*)d_in[1];
    const float* w1_0   = (const float*)d_in[2];
    const float* b1_0   = (const float*)d_in[3];
    const float* w2_0   = (const float*)d_in[4];
    const float* b2_0   = (const float*)d_in[5];
    const float* ws1    = (const float*)d_in[6];
    const float* bs1    = (const float*)d_in[7];
    const float* ws2    = (const float*)d_in[8];
    const float* bs2    = (const float*)d_in[9];
    const float* gammas = (const float*)d_in[10];
    const float* betas  = (const float*)d_in[11];
    const float* means  = (const float*)d_in[12];
    const float* vars   = (const float*)d_in[13];
    const float* fc1_w  = (const float*)d_in[14];
    const float* fc1_b  = (const float*)d_in[15];
    const float* fc2_w  = (const float*)d_in[16];
    const float* fc2_b  = (const float*)d_in[17];
    float* out = (float*)d_out;

    float *agg12, *h, *agg;
    cudaGetSymbolAddress((void**)&agg12, g_agg12);
    cudaGetSymbolAddress((void**)&h, g_h);
    cudaGetSymbolAddress((void**)&agg, g_agg);

    cudaFuncSetAttribute(mlp_mma<12, 16>, cudaFuncAttributeMaxDynamicSharedMemorySize, SM_TOTAL);
    cudaFuncSetAttribute(mlp_mma<128, 128>, cudaFuncAttributeMaxDynamicSharedMemorySize, SM_TOTAL);

    const int TC_GRID = (NN + 127) / 128;             // 391
    const int WARP_GRID = (NN * 32 + 255) / 256;      // one warp per node

    // ---- CSR build ----
    detect_kernel<<<1, 1>>>(ei);
    zero_counts_kernel<<<(NN + 255) / 256, 256>>>();
    hist_kernel<<<(NE + 255) / 256, 256>>>(ei);
    scan_reduce_kernel<<<NBLK, 256>>>();
    scan_sums_kernel<<<1, 64>>>();
    scan_final_kernel<<<NBLK, 1024>>>();
    fill_kernel<<<(NE + 255) / 256, 256>>>(ei);

    // ---- layer 1 (nfeat=12) ----
    gather12_kernel<<<WARP_GRID, 256>>>(x);
    mlp_mma<12, 16><<<TC_GRID, 256, SM_TOTAL>>>(agg12, w1_0, b1_0, w2_0, b2_0,
                                                gammas, betas, means, vars, h, 0);

    // ---- layers 2-5 ----
    for (int i = 0; i < 4; i++) {
        gather128_kernel<<<WARP_GRID, 256>>>(h, agg);
        mlp_mma<128, 128><<<TC_GRID, 256, SM_TOTAL>>>(agg,
                                                      ws1 + (size_t)i * D * D, bs1 + i * D,
                                                      ws2 + (size_t)i * D * D, bs2 + i * D,
                                                      gammas + (i + 1) * D, betas + (i + 1) * D,
                                                      means + (i + 1) * D, vars + (i + 1) * D,
                                                      h, 0);
    }

    // ---- head: fc1 (mma) + fc2 (SIMT) fused ----
    mlp_mma<128, 128><<<TC_GRID, 256, SM_TOTAL>>>(h, fc1_w, fc1_b, fc2_w, fc2_b,
                                                  nullptr, nullptr, nullptr, nullptr,
                                                  out, 1);
}

// round 11
// speedup vs baseline: 1.1518x; 1.1518x over previous
#include <cuda_runtime.h>
#include <cuda_bf16.h>
#include <cuda_fp16.h>
#include <cstdint>

#define NN   50000
#define NE   1600000
#define D    128
#define NCLS 6
#define NBLK 49          // ceil(NN / 1024) scan blocks

// ---------------- scratch (static device globals; no runtime allocation) ----
__device__ float  g_agg12[NN * 12];
__device__ float  g_h[(size_t)NN * D];
__device__ __half g_h16[(size_t)NN * D];
__device__ float  g_agg[(size_t)NN * D];
__device__ int    g_counts[NN];
__device__ int    g_rowptr[NN + 1];
__device__ int    g_cursor[NN];
__device__ int    g_col[NE];
__device__ int    g_blocksums[64];
__device__ int    g_blockoffs[64];
__device__ int    g_is64;   // 1 if edge_index really is int64, 0 if int32

// ---------------- small helpers ---------------------------------------------
__device__ __forceinline__ uint32_t smem_to_u32(const void* p) {
    uint32_t a;
    asm("{ .reg .u64 t; cvta.to.shared.u64 t, %1; cvt.u32.u64 %0, t; }"
        : "=r"(a) : "l"(p));
    return a;
}
__device__ __forceinline__ uint32_t lds32(uint32_t addr) {
    uint32_t v;
    asm volatile("ld.shared.b32 %0, [%1];" : "=r"(v) : "r"(addr));
    return v;
}
__device__ __forceinline__ void sts32(uint32_t addr, uint32_t v) {
    asm volatile("st.shared.b32 [%0], %1;" :: "r"(addr), "r"(v) : "memory");
}
// split two fp32 into bf16 hi/lo packed pairs
__device__ __forceinline__ void split2(float x, float y, uint32_t& hi, uint32_t& lo) {
    __nv_bfloat16 xh = __float2bfloat16(x), yh = __float2bfloat16(y);
    float xr = x - __bfloat162float(xh);
    float yr = y - __bfloat162float(yh);
    __nv_bfloat16 xl = __float2bfloat16(xr), yl = __float2bfloat16(yr);
    hi = ((uint32_t)__bfloat16_as_ushort(yh) << 16) | __bfloat16_as_ushort(xh);
    lo = ((uint32_t)__bfloat16_as_ushort(yl) << 16) | __bfloat16_as_ushort(xl);
}
__device__ __forceinline__ void mma16816(float* c, const uint32_t* a, const uint32_t* b) {
    asm volatile(
        "mma.sync.aligned.m16n8k16.row.col.f32.bf16.bf16.f32 "
        "{%0,%1,%2,%3},{%4,%5,%6,%7},{%8,%9},{%0,%1,%2,%3};"
        : "+f"(c[0]), "+f"(c[1]), "+f"(c[2]), "+f"(c[3])
        : "r"(a[0]), "r"(a[1]), "r"(a[2]), "r"(a[3]), "r"(b[0]), "r"(b[1]));
}
__device__ __forceinline__ void acc_h2(float4& a, uint2 p) {
    __half2 h0 = *reinterpret_cast<__half2*>(&p.x);
    __half2 h1 = *reinterpret_cast<__half2*>(&p.y);
    float2 f0 = __half22float2(h0);
    float2 f1 = __half22float2(h1);
    a.x += f0.x; a.y += f0.y; a.z += f1.x; a.w += f1.y;
}

// ---------------- smem tile layouts ------------------------------------------
#define KS 136                       // bf16 elems per row (padded)
__device__ __forceinline__ uint32_t a_off(int r, int k) {
    return (uint32_t)(r * KS + k) * 2;
}
// W tile: [n][k] with XOR swizzle on k bits 1..2 keyed by (n>>3)&3 —
// conflict-free for both transpose stores and b-fragment loads.
__device__ __forceinline__ uint32_t wt_off(int n, int k) {
    return (uint32_t)(n * KS + (k ^ ((((unsigned)n >> 3) & 3) << 1))) * 2;
}

#define SM_AHI   0
#define SM_ALO   34816
#define SM_W1HI  69632
#define SM_W1LO  104448
#define SM_W2HI  139264
#define SM_W2LO  174080
#define SM_PAR   208896              // 640 floats: b1|b2|sc|mn|bt
#define SM_TOTAL 211456

// ---------------- edge-index dtype detection --------------------------------
__global__ void detect_kernel(const void* ei) {
    const long long* p = (const long long*)ei;
    int ok = 1;
    for (int i = 0; i < 64; i++) {
        long long v = p[i];
        if (v < 0 || v >= NN) { ok = 0; break; }
    }
    g_is64 = ok;
}
__device__ __forceinline__ int edge_idx(const void* ei, long long pos, int is64) {
    if (is64) return (int)((const long long*)ei)[pos];
    return ((const int*)ei)[pos];
}

// ---------------- CSR build --------------------------------------------------
__global__ void zero_counts_kernel() {
    int i = blockIdx.x * blockDim.x + threadIdx.x;
    if (i < NN) g_counts[i] = 0;
}
__global__ void hist_kernel(const void* __restrict__ ei) {
    int e = blockIdx.x * blockDim.x + threadIdx.x;
    if (e >= NE) return;
    const int is64 = g_is64;
    int dst = edge_idx(ei, (long long)NE + e, is64);
    if ((unsigned)dst < NN) atomicAdd(&g_counts[dst], 1);
}
__global__ void scan_reduce_kernel() {
    __shared__ int sh[256];
    int base = blockIdx.x * 1024;
    int s = 0;
    for (int i = threadIdx.x; i < 1024; i += 256) {
        int idx = base + i;
        if (idx < NN) s += g_counts[idx];
    }
    sh[threadIdx.x] = s;
    __syncthreads();
    for (int off = 128; off > 0; off >>= 1) {
        if (threadIdx.x < off) sh[threadIdx.x] += sh[threadIdx.x + off];
        __syncthreads();
    }
    if (threadIdx.x == 0) g_blocksums[blockIdx.x] = sh[0];
}
__global__ void scan_sums_kernel() {
    __shared__ int sh[NBLK];
    if (threadIdx.x < NBLK) sh[threadIdx.x] = g_blocksums[threadIdx.x];
    __syncthreads();
    if (threadIdx.x == 0) {
        int run = 0;
        for (int i = 0; i < NBLK; i++) { int v = sh[i]; sh[i] = run; run += v; }
        g_rowptr[NN] = run;
    }
    __syncthreads();
    if (threadIdx.x < NBLK) g_blockoffs[threadIdx.x] = sh[threadIdx.x];
}
__global__ void scan_final_kernel() {
    __shared__ int sh[1024];
    int i = blockIdx.x * 1024 + threadIdx.x;
    int v = (i < NN) ? g_counts[i] : 0;
    sh[threadIdx.x] = v;
    __syncthreads();
#pragma unroll
    for (int off = 1; off < 1024; off <<= 1) {
        int t = (threadIdx.x >= off) ? sh[threadIdx.x - off] : 0;
        __syncthreads();
        sh[threadIdx.x] += t;
        __syncthreads();
    }
    if (i < NN) {
        int excl = g_blockoffs[blockIdx.x] + sh[threadIdx.x] - v;
        g_rowptr[i] = excl;
        g_cursor[i] = excl;
    }
}
__global__ void fill_kernel(const void* __restrict__ ei) {
    int e = blockIdx.x * blockDim.x + threadIdx.x;
    if (e >= NE) return;
    const int is64 = g_is64;
    int src = edge_idx(ei, e, is64);
    int dst = edge_idx(ei, (long long)NE + e, is64);
    if ((unsigned)src >= NN || (unsigned)dst >= NN) return;
    int pos = atomicAdd(&g_cursor[dst], 1);
    g_col[pos] = src;
}

// ---------------- CSR gather -------------------------------------------------
__global__ void gather12_kernel(const float* __restrict__ x) {
    int n = (blockIdx.x * blockDim.x + threadIdx.x) >> 5;
    if (n >= NN) return;
    int lane = threadIdx.x & 31;
    int beg = g_rowptr[n], end = g_rowptr[n + 1];
    float acc = (lane < 12) ? x[(size_t)n * 12 + lane] : 0.f;
    for (int e = beg; e < end; e++) {
        int s = g_col[e];
        if (lane < 12) acc += x[(size_t)s * 12 + lane];
    }
    if (lane < 12) g_agg12[(size_t)n * 12 + lane] = acc;
}
// fp16 neighbor gather: agg[n] = h_fp32[n] + sum h16[src].  One warp/node,
// lane owns 4 features (8B per row), 4 edges in flight.
__global__ void gather128_h16_kernel(const __half* __restrict__ h16,
                                     const float* __restrict__ h,
                                     float* __restrict__ agg) {
    int n = (blockIdx.x * blockDim.x + threadIdx.x) >> 5;
    if (n >= NN) return;
    int lane = threadIdx.x & 31;
    int beg = g_rowptr[n], end = g_rowptr[n + 1];
    const int fo = lane * 4;
    float4 acc = *reinterpret_cast<const float4*>(h + (size_t)n * D + fo);
    float4 acc2 = make_float4(0.f, 0.f, 0.f, 0.f);
    int e = beg;
    for (; e + 3 < end; e += 4) {
        int s0 = g_col[e], s1 = g_col[e + 1], s2 = g_col[e + 2], s3 = g_col[e + 3];
        uint2 p0 = *reinterpret_cast<const uint2*>(h16 + (size_t)s0 * D + fo);
        uint2 p1 = *reinterpret_cast<const uint2*>(h16 + (size_t)s1 * D + fo);
        uint2 p2 = *reinterpret_cast<const uint2*>(h16 + (size_t)s2 * D + fo);
        uint2 p3 = *reinterpret_cast<const uint2*>(h16 + (size_t)s3 * D + fo);
        acc_h2(acc, p0);  acc_h2(acc2, p1);
        acc_h2(acc, p2);  acc_h2(acc2, p3);
    }
    for (; e < end; e++) {
        uint2 p = *reinterpret_cast<const uint2*>(h16 + (size_t)g_col[e] * D + fo);
        acc_h2(acc, p);
    }
    acc.x += acc2.x; acc.y += acc2.y; acc.z += acc2.z; acc.w += acc2.w;
    *reinterpret_cast<float4*>(agg + (size_t)n * D + fo) = acc;
}

// ============================================================================
// mma.sync fused MLP: 128-row tile per CTA, 512 threads (16 warps, 4x4 grid).
// Warp (wr, wc): rows [32wr,32wr+32) as 2 m16 tiles, cols [32wc,32wc+32) as
// 4 n8 tiles: 32 LDS per 24 MMAs per k-step, 16 warps for latency hiding.
// bf16 hi/lo split, 3 passes (Ahi*Whi + Alo*Whi + Ahi*Wlo), fp32 accum.
// head==0: out = BN(relu( relu(A@W1+b1) @ W2 + b2 )), + fp16 copy to out16.
// head==1: fc1 (mma) + fc2 (SIMT).
// ============================================================================
__device__ __forceinline__ void gemm_split(
    uint32_t aHi, uint32_t aLo, uint32_t wHi, uint32_t wLo,
    int r0, int cc, int n0, int lane, float acc[2][4][4], int kpad) {
#pragma unroll 1
    for (int kb = 0; kb < kpad; kb += 16) {
        uint32_t ah[2][4], al[2][4];
#pragma unroll
        for (int m = 0; m < 2; m++) {
            int rm = r0 + m * 16;
            ah[m][0] = lds32(aHi + a_off(rm,     kb + cc));
            ah[m][1] = lds32(aHi + a_off(rm + 8, kb + cc));
            ah[m][2] = lds32(aHi + a_off(rm,     kb + cc + 8));
            ah[m][3] = lds32(aHi + a_off(rm + 8, kb + cc + 8));
            al[m][0] = lds32(aLo + a_off(rm,     kb + cc));
            al[m][1] = lds32(aLo + a_off(rm + 8, kb + cc));
            al[m][2] = lds32(aLo + a_off(rm,     kb + cc + 8));
            al[m][3] = lds32(aLo + a_off(rm + 8, kb + cc + 8));
        }
#pragma unroll
        for (int t = 0; t < 4; t++) {
            int nl = n0 + t * 8 + (lane >> 2);
            uint32_t bh[2], bl[2];
            bh[0] = lds32(wHi + wt_off(nl, kb + cc));
            bh[1] = lds32(wHi + wt_off(nl, kb + cc + 8));
            bl[0] = lds32(wLo + wt_off(nl, kb + cc));
            bl[1] = lds32(wLo + wt_off(nl, kb + cc + 8));
            mma16816(acc[0][t], ah[0], bh);
            mma16816(acc[1][t], ah[1], bh);
            mma16816(acc[0][t], al[0], bh);
            mma16816(acc[1][t], al[1], bh);
            mma16816(acc[0][t], ah[0], bl);
            mma16816(acc[1][t], ah[1], bl);
        }
    }
}

template <int KIN, int KPAD>
__global__ __launch_bounds__(512, 1) void mlp_mma(
    const float* __restrict__ A,
    const float* __restrict__ W1, const float* __restrict__ b1,
    const float* __restrict__ W2, const float* __restrict__ b2,
    const float* __restrict__ gamma, const float* __restrict__ beta,
    const float* __restrict__ mean, const float* __restrict__ var,
    float* __restrict__ out, __half* __restrict__ out16, int head) {
    extern __shared__ char smem[];
    const uint32_t sb = smem_to_u32(smem);
    const int tid = threadIdx.x;
    const int lane = tid & 31;
    const int wid = tid >> 5;
    const int wr = wid >> 2, wc = wid & 3;    // 4 x 4 warps
    const int row0 = blockIdx.x * 128;

    const uint32_t AHI = sb + SM_AHI, ALO = sb + SM_ALO;
    const uint32_t W1HI = sb + SM_W1HI, W1LO = sb + SM_W1LO;
    const uint32_t W2HI = sb + SM_W2HI, W2LO = sb + SM_W2LO;
    float* par = (float*)(smem + SM_PAR);   // b1[128] b2[128] sc[128] mn[128] bt[128]

    // ---- stage A [row][k] hi/lo ----
    {
        int r = tid >> 2, q = tid & 3;
        int gr = row0 + r;
        const float* ar = A + (size_t)gr * KIN;
        bool ok = gr < NN;
#pragma unroll
        for (int j = 0; j < KPAD / 16; j++) {
            int k = q * (KPAD / 4) + j * 4;
            float4 v = make_float4(0.f, 0.f, 0.f, 0.f);
            if (ok) {
                if (k + 3 < KIN) v = *reinterpret_cast<const float4*>(ar + k);
                else {
                    if (k     < KIN) v.x = ar[k];
                    if (k + 1 < KIN) v.y = ar[k + 1];
                    if (k + 2 < KIN) v.z = ar[k + 2];
                    if (k + 3 < KIN) v.w = ar[k + 3];
                }
            }
            uint32_t h0, l0, h1, l1;
            split2(v.x, v.y, h0, l0);
            split2(v.z, v.w, h1, l1);
            sts32(AHI + a_off(r, k),     h0);
            sts32(AHI + a_off(r, k + 2), h1);
            sts32(ALO + a_off(r, k),     l0);
            sts32(ALO + a_off(r, k + 2), l1);
        }
    }
    // ---- stage W1 transposed [n][k] hi/lo (coalesced gmem reads) ----
    {
        int n = tid & 127;
        int ko = (tid >> 7) * 2;   // 0,2,4,6
        for (int kk = 0; kk < KPAD; kk += 8) {
            int k = kk + ko;
            float v0 = (k     < KIN) ? __ldg(W1 + (size_t)k * D + n) : 0.f;
            float v1 = (k + 1 < KIN) ? __ldg(W1 + (size_t)(k + 1) * D + n) : 0.f;
            uint32_t hi, lo;
            split2(v0, v1, hi, lo);
            sts32(W1HI + wt_off(n, k), hi);
            sts32(W1LO + wt_off(n, k), lo);
        }
    }
    // ---- stage W2 ----
    if (!head) {
        int n = tid & 127;
        int ko = (tid >> 7) * 2;
        for (int kk = 0; kk < 128; kk += 8) {
            int k = kk + ko;
            float v0 = __ldg(W2 + (size_t)k * D + n);
            float v1 = __ldg(W2 + (size_t)(k + 1) * D + n);
            uint32_t hi, lo;
            split2(v0, v1, hi, lo);
            sts32(W2HI + wt_off(n, k), hi);
            sts32(W2LO + wt_off(n, k), lo);
        }
    } else {
        float* w2f = (float*)(smem + SM_W2HI);
        for (int i = tid; i < D * NCLS; i += 512) w2f[i] = __ldg(W2 + i);
    }
    // ---- stage params ----
    if (tid < 128) {
        par[tid] = __ldg(b1 + tid);
        if (!head) {
            par[128 + tid] = __ldg(b2 + tid);
            par[256 + tid] = __ldg(gamma + tid) * rsqrtf(__ldg(var + tid) + 1e-5f);
            par[384 + tid] = __ldg(mean + tid);
            par[512 + tid] = __ldg(beta + tid);
        } else if (tid < NCLS) {
            par[128 + tid] = __ldg(b2 + tid);
        }
    }
    __syncthreads();

    const int r0 = wr * 32 + (lane >> 2);
    const int cc = (lane & 3) * 2;
    const int n0 = wc * 32;

    // ---- GEMM1 ----
    float acc[2][4][4];
#pragma unroll
    for (int m = 0; m < 2; m++)
#pragma unroll
        for (int t = 0; t < 4; t++)
#pragma unroll
            for (int j = 0; j < 4; j++) acc[m][t][j] = 0.f;
    gemm_split(AHI, ALO, W1HI, W1LO, r0, cc, n0, lane, acc, KPAD);
    __syncthreads();   // all A/W1 reads done before overwriting A with T

    // ---- epilogue1: T = relu(acc + b1) -> back into A slots ----
    if (!head) {
#pragma unroll
        for (int m = 0; m < 2; m++) {
            int rm = r0 + m * 16;
#pragma unroll
            for (int t = 0; t < 4; t++) {
                int c0 = n0 + t * 8 + cc;
                float x0 = fmaxf(acc[m][t][0] + par[c0], 0.f);
                float x1 = fmaxf(acc[m][t][1] + par[c0 + 1], 0.f);
                float x2 = fmaxf(acc[m][t][2] + par[c0], 0.f);
                float x3 = fmaxf(acc[m][t][3] + par[c0 + 1], 0.f);
                uint32_t h, l;
                split2(x0, x1, h, l);
                sts32(AHI + a_off(rm, c0), h);
                sts32(ALO + a_off(rm, c0), l);
                split2(x2, x3, h, l);
                sts32(AHI + a_off(rm + 8, c0), h);
                sts32(ALO + a_off(rm + 8, c0), l);
            }
        }
    } else {
        float* Tf = (float*)(smem + SM_AHI);   // fp32, stride 132
#pragma unroll
        for (int m = 0; m < 2; m++) {
            int rm = r0 + m * 16;
#pragma unroll
            for (int t = 0; t < 4; t++) {
                int c0 = n0 + t * 8 + cc;
                Tf[rm * 132 + c0]           = fmaxf(acc[m][t][0] + par[c0], 0.f);
                Tf[rm * 132 + c0 + 1]       = fmaxf(acc[m][t][1] + par[c0 + 1], 0.f);
                Tf[(rm + 8) * 132 + c0]     = fmaxf(acc[m][t][2] + par[c0], 0.f);
                Tf[(rm + 8) * 132 + c0 + 1] = fmaxf(acc[m][t][3] + par[c0 + 1], 0.f);
            }
        }
    }
    __syncthreads();

    if (head) {
        // ---- fc2 SIMT: out[128x6] = T @ W2 + b2 ----
        if (tid < 128) {
            const float* Tf = (const float*)(smem + SM_AHI);
            const float* Wf = (const float*)(smem + SM_W2HI);
            float a6[NCLS];
#pragma unroll
            for (int c = 0; c < NCLS; c++) a6[c] = par[128 + c];
            for (int kk = 0; kk < D; kk++) {
                int k = (kk + lane) & (D - 1);
                float tv = Tf[tid * 132 + k];
#pragma unroll
                for (int c = 0; c < NCLS; c++) a6[c] += tv * Wf[k * NCLS + c];
            }
            if (row0 + tid < NN)
#pragma unroll
                for (int c = 0; c < NCLS; c++) out[(size_t)(row0 + tid) * NCLS + c] = a6[c];
        }
        return;
    }

    // ---- GEMM2 ----
#pragma unroll
    for (int m = 0; m < 2; m++)
#pragma unroll
        for (int t = 0; t < 4; t++)
#pragma unroll
            for (int j = 0; j < 4; j++) acc[m][t][j] = 0.f;
    gemm_split(AHI, ALO, W2HI, W2LO, r0, cc, n0, lane, acc, 128);

    // ---- epilogue2: BN(relu(acc + b2)) -> gmem fp32 + fp16 copy ----
#pragma unroll
    for (int m = 0; m < 2; m++) {
        int g0 = row0 + r0 + m * 16, g1 = g0 + 8;
#pragma unroll
        for (int t = 0; t < 4; t++) {
            int c0 = n0 + t * 8 + cc;
            float b0v = par[128 + c0], b1v = par[128 + c0 + 1];
            float s0 = par[256 + c0],  s1 = par[256 + c0 + 1];
            float m0 = par[384 + c0],  m1 = par[384 + c0 + 1];
            float t0 = par[512 + c0],  t1 = par[512 + c0 + 1];
            if (g0 < NN) {
                float v0 = (fmaxf(acc[m][t][0] + b0v, 0.f) - m0) * s0 + t0;
                float v1 = (fmaxf(acc[m][t][1] + b1v, 0.f) - m1) * s1 + t1;
                *reinterpret_cast<float2*>(out + (size_t)g0 * D + c0) = make_float2(v0, v1);
                *reinterpret_cast<__half2*>(out16 + (size_t)g0 * D + c0) =
                    __floats2half2_rn(v0, v1);
            }
            if (g1 < NN) {
                float v2 = (fmaxf(acc[m][t][2] + b0v, 0.f) - m0) * s0 + t0;
                float v3 = (fmaxf(acc[m][t][3] + b1v, 0.f) - m1) * s1 + t1;
                *reinterpret_cast<float2*>(out + (size_t)g1 * D + c0) = make_float2(v2, v3);
                *reinterpret_cast<__half2*>(out16 + (size_t)g1 * D + c0) =
                    __floats2half2_rn(v2, v3);
            }
        }
    }
}

// ---------------- launch ----------------------------------------------------
extern "C" void kernel_launch(void* const* d_in, const int* in_sizes, int n_in,
                              void* d_out, int out_size) {
    const float* x      = (const float*)d_in[0];
    const void*  ei     = (const void*)d_in[1];
    const float* w1_0   = (const float*)d_in[2];
    const float* b1_0   = (const float*)d_in[3];
    const float* w2_0   = (const float*)d_in[4];
    const float* b2_0   = (const float*)d_in[5];
    const float* ws1    = (const float*)d_in[6];
    const float* bs1    = (const float*)d_in[7];
    const float* ws2    = (const float*)d_in[8];
    const float* bs2    = (const float*)d_in[9];
    const float* gammas = (const float*)d_in[10];
    const float* betas  = (const float*)d_in[11];
    const float* means  = (const float*)d_in[12];
    const float* vars   = (const float*)d_in[13];
    const float* fc1_w  = (const float*)d_in[14];
    const float* fc1_b  = (const float*)d_in[15];
    const float* fc2_w  = (const float*)d_in[16];
    const float* fc2_b  = (const float*)d_in[17];
    float* out = (float*)d_out;

    float *agg12, *h, *agg;
    __half* h16;
    cudaGetSymbolAddress((void**)&agg12, g_agg12);
    cudaGetSymbolAddress((void**)&h, g_h);
    cudaGetSymbolAddress((void**)&h16, g_h16);
    cudaGetSymbolAddress((void**)&agg, g_agg);

    cudaFuncSetAttribute(mlp_mma<12, 16>, cudaFuncAttributeMaxDynamicSharedMemorySize, SM_TOTAL);
    cudaFuncSetAttribute(mlp_mma<128, 128>, cudaFuncAttributeMaxDynamicSharedMemorySize, SM_TOTAL);

    const int TC_GRID = (NN + 127) / 128;             // 391
    const int WARP_GRID = (NN * 32 + 255) / 256;      // one warp per node

    // ---- CSR build ----
    detect_kernel<<<1, 1>>>(ei);
    zero_counts_kernel<<<(NN + 255) / 256, 256>>>();
    hist_kernel<<<(NE + 255) / 256, 256>>>(ei);
    scan_reduce_kernel<<<NBLK, 256>>>();
    scan_sums_kernel<<<1, 64>>>();
    scan_final_kernel<<<NBLK, 1024>>>();
    fill_kernel<<<(NE + 255) / 256, 256>>>(ei);

    // ---- layer 1 (nfeat=12) ----
    gather12_kernel<<<WARP_GRID, 256>>>(x);
    mlp_mma<12, 16><<<TC_GRID, 512, SM_TOTAL>>>(agg12, w1_0, b1_0, w2_0, b2_0,
                                                gammas, betas, means, vars, h, h16, 0);

    // ---- layers 2-5 ----
    for (int i = 0; i < 4; i++) {
        gather128_h16_kernel<<<WARP_GRID, 256>>>(h16, h, agg);
        mlp_mma<128, 128><<<TC_GRID, 512, SM_TOTAL>>>(agg,
                                                      ws1 + (size_t)i * D * D, bs1 + i * D,
                                                      ws2 + (size_t)i * D * D, bs2 + i * D,
                                                      gammas + (i + 1) * D, betas + (i + 1) * D,
                                                      means + (i + 1) * D, vars + (i + 1) * D,
                                                      h, h16, 0);
    }

    // ---- head: fc1 (mma) + fc2 (SIMT) fused ----
    mlp_mma<128, 128><<<TC_GRID, 512, SM_TOTAL>>>(h, fc1_w, fc1_b, fc2_w, fc2_b,
                                                  nullptr, nullptr, nullptr, nullptr,
                                                  out, nullptr, 1);
}